// round 4
// baseline (speedup 1.0000x reference)
#include <cuda_runtime.h>
#include <cuda_bf16.h>
#include <cstdint>

// Nearest-of-16-sorted-qpoints quantizer, round 3.
// R2 hit 82us: DRAM 78.2%, alu 43.9%, L1 65.5% -> memory-bound.
// R3: raise DRAM toward ceiling. 4x float4 per thread with front-batched
// streaming loads (__ldcs, MLP_p1=4), batched streaming stores (__stcs),
// same 4-level branchless binary search (semantics identical, rel_err==0).

__device__ __forceinline__ float quant1(float v, float m7,
                                        const float* __restrict__ s_mid,
                                        const float* __restrict__ s_qp)
{
    int i = (v > m7) ? 8 : 0;              // level 0: uniform register compare
    i += (v > s_mid[i + 3]) ? 4 : 0;       // level 1: LDS
    i += (v > s_mid[i + 1]) ? 2 : 0;       // level 2: LDS
    i += (v > s_mid[i]) ? 1 : 0;           // level 3: LDS
    return s_qp[i];                         // value LUT: LDS, broadcast-friendly
}

__device__ __forceinline__ float4 quant4(float4 v, float m7,
                                         const float* __restrict__ s_mid,
                                         const float* __restrict__ s_qp)
{
    float4 o;
    o.x = quant1(v.x, m7, s_mid, s_qp);
    o.y = quant1(v.y, m7, s_mid, s_qp);
    o.z = quant1(v.z, m7, s_mid, s_qp);
    o.w = quant1(v.w, m7, s_mid, s_qp);
    return o;
}

__global__ __launch_bounds__(256) void QPointQuantize_kernel(
    const float4* __restrict__ x,
    const float* __restrict__ q,
    float4* __restrict__ out,
    int n4)
{
    __shared__ float s_qp[16];
    __shared__ float s_mid[16];   // 15 used; banks 0-14, conflict-free

    if (threadIdx.x < 16)
        s_qp[threadIdx.x] = q[threadIdx.x];
    __syncthreads();
    if (threadIdx.x < 15)
        s_mid[threadIdx.x] = 0.5f * (s_qp[threadIdx.x] + s_qp[threadIdx.x + 1]);
    __syncthreads();

    const float m7 = s_mid[7];    // uniform -> register, skips one LDS level

    // 4 float4 per thread; all loads front-batched for MLP_p1=4.
    int base = blockIdx.x * (256 * 4) + threadIdx.x;

    if (base + 3 * 256 < n4) {
        // Streaming loads: evict-first in L2 (data is touched exactly once).
        float4 v0 = __ldcs(&x[base]);
        float4 v1 = __ldcs(&x[base + 256]);
        float4 v2 = __ldcs(&x[base + 512]);
        float4 v3 = __ldcs(&x[base + 768]);

        float4 o0 = quant4(v0, m7, s_mid, s_qp);
        float4 o1 = quant4(v1, m7, s_mid, s_qp);
        float4 o2 = quant4(v2, m7, s_mid, s_qp);
        float4 o3 = quant4(v3, m7, s_mid, s_qp);

        __stcs(&out[base],       o0);
        __stcs(&out[base + 256], o1);
        __stcs(&out[base + 512], o2);
        __stcs(&out[base + 768], o3);
    } else {
        // Tail safety (exact divide for this shape, but keep it correct)
        for (int k = 0; k < 4; k++) {
            int idx = base + k * 256;
            if (idx < n4) {
                float4 v = __ldcs(&x[idx]);
                __stcs(&out[idx], quant4(v, m7, s_mid, s_qp));
            }
        }
    }
}

extern "C" void kernel_launch(void* const* d_in, const int* in_sizes, int n_in,
                              void* d_out, int out_size)
{
    const float* x = (const float*)d_in[0];   // (64, 1024, 1024) fp32
    const float* q = (const float*)d_in[1];   // (16,) fp32 sorted
    float* out = (float*)d_out;

    int n = in_sizes[0];          // 67,108,864
    int n4 = n >> 2;              // 16,777,216 float4s

    int threads = 256;
    int elems_per_block = threads * 4;                     // 1024 float4s
    int blocks = (n4 + elems_per_block - 1) / elems_per_block;  // 16,384

    QPointQuantize_kernel<<<blocks, threads>>>(
        (const float4*)x, q, (float4*)out, n4);
}

// round 5
// speedup vs baseline: 1.1123x; 1.1123x over previous
#include <cuda_runtime.h>
#include <cuda_bf16.h>
#include <cstdint>

// Nearest-of-16-sorted-qpoints quantizer, round 4.
// R2 (2x float4, 32 regs, occ 86%) = 82us @ DRAM 78.2%.
// R3 (4x float4) regressed: regs 39 -> occ 64% -> DRAM 71%. Reverted.
// R4 = exact R2 structure + streaming cache hints only:
//   __ldcs on loads, __stcs on stores -> stop write-once/read-once data
//   from churning L2, free LTS capacity for read fills.

__device__ __forceinline__ float quant1(float v, float m7,
                                        const float* __restrict__ s_mid,
                                        const float* __restrict__ s_qp)
{
    int i = (v > m7) ? 8 : 0;              // level 0: uniform register compare
    i += (v > s_mid[i + 3]) ? 4 : 0;       // level 1: LDS
    i += (v > s_mid[i + 1]) ? 2 : 0;       // level 2: LDS
    i += (v > s_mid[i]) ? 1 : 0;           // level 3: LDS
    return s_qp[i];                         // value LUT: LDS broadcast
}

__global__ __launch_bounds__(256) void QPointQuantize_kernel(
    const float4* __restrict__ x,
    const float* __restrict__ q,
    float4* __restrict__ out,
    int n4)
{
    __shared__ float s_qp[16];
    __shared__ float s_mid[16];   // 15 used; banks 0-14, conflict-free

    if (threadIdx.x < 16)
        s_qp[threadIdx.x] = q[threadIdx.x];
    __syncthreads();
    if (threadIdx.x < 15)
        s_mid[threadIdx.x] = 0.5f * (s_qp[threadIdx.x] + s_qp[threadIdx.x + 1]);
    __syncthreads();

    const float m7 = s_mid[7];    // uniform -> register, skips one LDS level

    // 2 float4 per thread, coalesced, front-batched loads (MLP_p1=2).
    int base = blockIdx.x * (256 * 2) + threadIdx.x;

    if (base + 256 < n4) {
        float4 v0 = __ldcs(&x[base]);
        float4 v1 = __ldcs(&x[base + 256]);

        float4 o0, o1;
        o0.x = quant1(v0.x, m7, s_mid, s_qp);
        o0.y = quant1(v0.y, m7, s_mid, s_qp);
        o0.z = quant1(v0.z, m7, s_mid, s_qp);
        o0.w = quant1(v0.w, m7, s_mid, s_qp);
        o1.x = quant1(v1.x, m7, s_mid, s_qp);
        o1.y = quant1(v1.y, m7, s_mid, s_qp);
        o1.z = quant1(v1.z, m7, s_mid, s_qp);
        o1.w = quant1(v1.w, m7, s_mid, s_qp);

        __stcs(&out[base],       o0);
        __stcs(&out[base + 256], o1);
    } else {
        for (int k = 0; k < 2; k++) {
            int idx = base + k * 256;
            if (idx < n4) {
                float4 v = __ldcs(&x[idx]);
                float4 o;
                o.x = quant1(v.x, m7, s_mid, s_qp);
                o.y = quant1(v.y, m7, s_mid, s_qp);
                o.z = quant1(v.z, m7, s_mid, s_qp);
                o.w = quant1(v.w, m7, s_mid, s_qp);
                __stcs(&out[idx], o);
            }
        }
    }
}

extern "C" void kernel_launch(void* const* d_in, const int* in_sizes, int n_in,
                              void* d_out, int out_size)
{
    const float* x = (const float*)d_in[0];   // (64, 1024, 1024) fp32
    const float* q = (const float*)d_in[1];   // (16,) fp32 sorted
    float* out = (float*)d_out;

    int n = in_sizes[0];          // 67,108,864
    int n4 = n >> 2;              // 16,777,216 float4s

    int threads = 256;
    int elems_per_block = threads * 2;                     // 512 float4s
    int blocks = (n4 + elems_per_block - 1) / elems_per_block;  // 32,768

    QPointQuantize_kernel<<<blocks, threads>>>(
        (const float4*)x, q, (float4*)out, n4);
}